// round 17
// baseline (speedup 1.0000x reference)
#include <cuda_runtime.h>

// ---------------- problem constants ----------------
#define BB    64    // batch
#define NNv   64    // news per batch
#define HLv   50    // history length
#define INv   384   // input dim
#define POSv  64    // pos-emb dim
#define ATTv  256   // attention hidden dim
#define NEWSv 448   // IN + POS
#define W1LD  896   // W1 row stride (2*NEWS)
#define AROWS (BB * NNv + BB * HLv)   // 7296 rows of A (PN rows then PL rows)

// ---------------- device scratch (no allocations allowed) ----------------
__device__ float g_PN[BB * NNv * ATTv];    // pn + t0   [4096, 256]
__device__ float g_PL[BB * HLv * ATTv];    // pl + posW [3200, 256]
__device__ float g_t0[ATTv];               // b1 + pos0 @ Wn_pos
__device__ float g_posW[HLv * ATTv];       // pos_emb[1+h] @ Wl_pos
__device__ float g_W1hi[ATTv * W1LD];      // tf32-hi split of W1
__device__ float g_W1lo[ATTv * W1LD];      // tf32-lo split of W1
__device__ float g_Ahi[AROWS * INv];       // tf32-hi split of [news; logv]
__device__ float g_Alo[AROWS * INv];       // tf32-lo split

__device__ __forceinline__ float tanh_fast(float x) {
    float y;
    asm("tanh.approx.f32 %0, %1;" : "=f"(y) : "f"(x));
    return y;
}

__device__ __forceinline__ unsigned tf32_rna(float x) {
    unsigned u;
    asm("cvt.rna.tf32.f32 %0, %1;" : "=r"(u) : "f"(x));
    return u;
}

// c[4] += A(tf32 m16k8) * B(tf32 k8n8)
#define MMA_TF32(cc, aa, bb)                                                     \
    asm("mma.sync.aligned.m16n8k8.row.col.f32.tf32.tf32.f32 "                    \
        "{%0,%1,%2,%3}, {%4,%5,%6,%7}, {%8,%9}, {%0,%1,%2,%3};"                  \
        : "+f"(cc[0]), "+f"(cc[1]), "+f"(cc[2]), "+f"(cc[3])                     \
        : "r"(aa[0]), "r"(aa[1]), "r"(aa[2]), "r"(aa[3]), "r"(bb[0]), "r"(bb[1]))

#define CP_ASYNC16(smem_u32, gptr)                                               \
    asm volatile("cp.async.ca.shared.global [%0], [%1], 16;\n" ::                \
                 "r"(smem_u32), "l"(gptr))

// ---------------- K0: tiny precompute of t0 and posW ----------------
__global__ void prep_kernel(const float* __restrict__ pos_emb,
                            const float* __restrict__ W1,
                            const float* __restrict__ b1) {
    int a = threadIdx.x;  // 0..255
    if (blockIdx.x == 0) {
        float s = b1[a];
#pragma unroll
        for (int j = 0; j < POSv; j++)
            s += pos_emb[j] * W1[a * W1LD + INv + j];
        g_t0[a] = s;
    } else {
        int h = blockIdx.x - 1;  // 0..49
        float s = 0.f;
#pragma unroll
        for (int j = 0; j < POSv; j++)
            s += pos_emb[(1 + h) * POSv + j] * W1[a * W1LD + NEWSv + INv + j];
        g_posW[h * ATTv + a] = s;
    }
}

// ---------------- K0b: pre-split W1 into tf32 hi/lo ----------------
__global__ void split_w1_kernel(const float* __restrict__ W1) {
    int a = blockIdx.x;            // 0..255
    int c = threadIdx.x * 4;       // 0..892
    if (c >= W1LD) return;
    float4 v = *(const float4*)(W1 + (size_t)a * W1LD + c);
    float h0 = __uint_as_float(tf32_rna(v.x));
    float h1 = __uint_as_float(tf32_rna(v.y));
    float h2 = __uint_as_float(tf32_rna(v.z));
    float h3 = __uint_as_float(tf32_rna(v.w));
    *(float4*)(g_W1hi + (size_t)a * W1LD + c) = make_float4(h0, h1, h2, h3);
    *(float4*)(g_W1lo + (size_t)a * W1LD + c) = make_float4(
        __uint_as_float(tf32_rna(v.x - h0)), __uint_as_float(tf32_rna(v.y - h1)),
        __uint_as_float(tf32_rna(v.z - h2)), __uint_as_float(tf32_rna(v.w - h3)));
}

// ---------------- K0c: pre-split A = [news ; logv] into tf32 hi/lo ----------
__global__ void asplit_kernel(const float4* __restrict__ news4,
                              const float4* __restrict__ logv4) {
    size_t idx = (size_t)blockIdx.x * 256 + threadIdx.x;  // float4 index
    const size_t nTot = (size_t)AROWS * INv / 4;
    if (idx >= nTot) return;
    const size_t nNews = (size_t)BB * NNv * INv / 4;
    float4 v = (idx < nNews) ? news4[idx] : logv4[idx - nNews];
    float h0 = __uint_as_float(tf32_rna(v.x));
    float h1 = __uint_as_float(tf32_rna(v.y));
    float h2 = __uint_as_float(tf32_rna(v.z));
    float h3 = __uint_as_float(tf32_rna(v.w));
    ((float4*)g_Ahi)[idx] = make_float4(h0, h1, h2, h3);
    ((float4*)g_Alo)[idx] = make_float4(
        __uint_as_float(tf32_rna(v.x - h0)), __uint_as_float(tf32_rna(v.y - h1)),
        __uint_as_float(tf32_rna(v.z - h2)), __uint_as_float(tf32_rna(v.w - h3)));
}

// ---------------- K1: nf output (pure copy/broadcast, float4) ----------------
__global__ void nf_kernel(const float4* __restrict__ news4,
                          const float4* __restrict__ pos4,
                          float4* __restrict__ out4) {
    int bn = blockIdx.x;      // 0..4095
    int d4 = threadIdx.x;     // 0..111
    if (d4 >= NEWSv / 4) return;
    float4 v = (d4 < INv / 4) ? news4[bn * (INv / 4) + d4] : pos4[d4 - INv / 4];
    out4[bn * (NEWSv / 4) + d4] = v;
}

// ---------------- K2: tensor-core GEMMs, 3xTF32, cp.async double-buffer -----
// C[m,a] = sum_k A[m,k] * W1[a, colofs+k] + bias. CTA tile 64x64, 8 warps
// (4x2), warp tile 16x32, KC=16, 2-stage cp.async pipeline.
#define KC  16
#define SLD 20   // smem row stride (floats); conflict-free for frag patterns
#define NC  (INv / KC)   // 24 chunks

__global__ __launch_bounds__(256) void gemm_tc_kernel() {
    const int isPL = blockIdx.z;
    float* C;
    size_t abase;
    int colofs;
    if (isPL) {
        if (blockIdx.y >= 50) return;
        abase = (size_t)BB * NNv * INv; C = g_PL; colofs = NEWSv;
    } else {
        abase = 0; C = g_PN; colofs = 0;
    }
    const int m0 = blockIdx.y * 64;
    const int n0 = blockIdx.x * 64;

    __shared__ __align__(16) float Ah[2][64 * SLD], Al[2][64 * SLD];
    __shared__ __align__(16) float Bh[2][64 * SLD], Bl[2][64 * SLD];

    const int tid = threadIdx.x;
    const int wid = tid >> 5, lane = tid & 31;
    const int wm = wid >> 1, wn = wid & 1;       // 4x2 warp grid
    const int g = lane >> 2, tg = lane & 3;      // groupID, threadInGroup

    // loader: thread handles row r, k-quad q (one 16B chunk per matrix)
    const int lr = tid >> 2;        // 0..63
    const int lq = (tid & 3) * 4;   // 0,4,8,12

    const float* srcAh = g_Ahi + abase + (size_t)(m0 + lr) * INv + lq;
    const float* srcAl = g_Alo + abase + (size_t)(m0 + lr) * INv + lq;
    const float* srcBh = g_W1hi + (size_t)(n0 + lr) * W1LD + colofs + lq;
    const float* srcBl = g_W1lo + (size_t)(n0 + lr) * W1LD + colofs + lq;
    const int dstoff = lr * SLD + lq;

    float c[4][4];
#pragma unroll
    for (int nt = 0; nt < 4; nt++)
#pragma unroll
        for (int i = 0; i < 4; i++) c[nt][i] = 0.f;

    // prologue: stage 0
    {
        unsigned a0 = (unsigned)__cvta_generic_to_shared(&Ah[0][dstoff]);
        unsigned a1 = (unsigned)__cvta_generic_to_shared(&Al[0][dstoff]);
        unsigned a2 = (unsigned)__cvta_generic_to_shared(&Bh[0][dstoff]);
        unsigned a3 = (unsigned)__cvta_generic_to_shared(&Bl[0][dstoff]);
        CP_ASYNC16(a0, srcAh); CP_ASYNC16(a1, srcAl);
        CP_ASYNC16(a2, srcBh); CP_ASYNC16(a3, srcBl);
        asm volatile("cp.async.commit_group;\n" ::);
    }

    for (int ch = 0; ch < NC; ch++) {
        const int s = ch & 1;
        if (ch + 1 < NC) {
            const int s1 = (ch + 1) & 1;
            const int ko = (ch + 1) * KC;
            unsigned a0 = (unsigned)__cvta_generic_to_shared(&Ah[s1][dstoff]);
            unsigned a1 = (unsigned)__cvta_generic_to_shared(&Al[s1][dstoff]);
            unsigned a2 = (unsigned)__cvta_generic_to_shared(&Bh[s1][dstoff]);
            unsigned a3 = (unsigned)__cvta_generic_to_shared(&Bl[s1][dstoff]);
            CP_ASYNC16(a0, srcAh + ko); CP_ASYNC16(a1, srcAl + ko);
            CP_ASYNC16(a2, srcBh + ko); CP_ASYNC16(a3, srcBl + ko);
            asm volatile("cp.async.commit_group;\n" ::);
            asm volatile("cp.async.wait_group 1;\n" ::);
        } else {
            asm volatile("cp.async.wait_group 0;\n" ::);
        }
        __syncthreads();

#pragma unroll
        for (int ks = 0; ks < 2; ks++) {
            const int kb = ks * 8;
            const int r = wm * 16 + g;
            unsigned ah[4], al[4];
            ah[0] = __float_as_uint(Ah[s][r * SLD + kb + tg]);
            ah[1] = __float_as_uint(Ah[s][(r + 8) * SLD + kb + tg]);
            ah[2] = __float_as_uint(Ah[s][r * SLD + kb + tg + 4]);
            ah[3] = __float_as_uint(Ah[s][(r + 8) * SLD + kb + tg + 4]);
            al[0] = __float_as_uint(Al[s][r * SLD + kb + tg]);
            al[1] = __float_as_uint(Al[s][(r + 8) * SLD + kb + tg]);
            al[2] = __float_as_uint(Al[s][r * SLD + kb + tg + 4]);
            al[3] = __float_as_uint(Al[s][(r + 8) * SLD + kb + tg + 4]);
            unsigned bh[4][2], bl[4][2];
#pragma unroll
            for (int nt = 0; nt < 4; nt++) {
                const int rb = wn * 32 + nt * 8 + g;
                bh[nt][0] = __float_as_uint(Bh[s][rb * SLD + kb + tg]);
                bh[nt][1] = __float_as_uint(Bh[s][rb * SLD + kb + tg + 4]);
                bl[nt][0] = __float_as_uint(Bl[s][rb * SLD + kb + tg]);
                bl[nt][1] = __float_as_uint(Bl[s][rb * SLD + kb + tg + 4]);
            }
#pragma unroll
            for (int nt = 0; nt < 4; nt++) {
                MMA_TF32(c[nt], ah, bh[nt]);
                MMA_TF32(c[nt], ah, bl[nt]);
                MMA_TF32(c[nt], al, bh[nt]);
            }
        }
        __syncthreads();
    }

    // epilogue: c0,c1 -> (row g, cols 2tg,2tg+1); c2,c3 -> row g+8
    const int m1 = m0 + wm * 16 + g;
    const int m2 = m1 + 8;
    const float* bp1 = isPL ? (g_posW + (m1 % HLv) * ATTv) : g_t0;
    const float* bp2 = isPL ? (g_posW + (m2 % HLv) * ATTv) : g_t0;
#pragma unroll
    for (int nt = 0; nt < 4; nt++) {
        const int a = n0 + wn * 32 + nt * 8 + 2 * tg;
        *(float2*)(C + (size_t)m1 * ATTv + a) =
            make_float2(c[nt][0] + bp1[a], c[nt][1] + bp1[a + 1]);
        *(float2*)(C + (size_t)m2 * ATTv + a) =
            make_float2(c[nt][2] + bp2[a], c[nt][3] + bp2[a + 1]);
    }
}

// ---------------- K3: logits + softmax + output GEMM (R11, proven) ---------
#define N_PER_CTA 4

__global__ __launch_bounds__(256) void attn_kernel(const float* __restrict__ logv,
                                                   const int*   __restrict__ mask,
                                                   const float* __restrict__ pos_emb,
                                                   const float* __restrict__ W2,
                                                   const float* __restrict__ b2,
                                                   float* __restrict__ out) {
    const int b = blockIdx.y;
    const int nbase = blockIdx.x * N_PER_CTA;

    __shared__ __align__(16) float pnS[N_PER_CTA][ATTv];
    __shared__ float attnS[N_PER_CTA][HLv + 2];
    __shared__ int maskS[HLv];
    __shared__ short listS[HLv];
    __shared__ int cntS;

    const int tid = threadIdx.x;
    const int w = tid >> 5, lane = tid & 31;

    ((float4*)&pnS[0][0])[tid] =
        ((const float4*)(g_PN + (size_t)(b * NNv + nbase) * ATTv))[tid];
    if (tid < HLv) maskS[tid] = mask[b * HLv + tid];

    float w2r[8];
#pragma unroll
    for (int i = 0; i < 8; i++) w2r[i] = W2[lane + 32 * i];
    const float b2v = b2[0];
    __syncthreads();

    if (tid == 0) {
        int c = 0;
        for (int h = 0; h < HLv; h++)
            if (maskS[h] != 0) listS[c++] = (short)h;
        cntS = c;
    }
    if (tid < HLv && maskS[tid] == 0) {
#pragma unroll
        for (int n = 0; n < N_PER_CTA; n++) attnS[n][tid] = -1e9f;
    }
    __syncthreads();
    const int cnt = cntS;

    for (int idx = w; idx < cnt; idx += 8) {
        const int h = listS[idx];
        const float* pl = g_PL + (size_t)(b * HLv + h) * ATTv;
        float plr[8];
#pragma unroll
        for (int i = 0; i < 8; i++) plr[i] = pl[lane + 32 * i];

        float s[N_PER_CTA];
#pragma unroll
        for (int n = 0; n < N_PER_CTA; n++) s[n] = 0.f;
#pragma unroll
        for (int i = 0; i < 8; i++) {
            const float pv = plr[i];
            const float wv = w2r[i];
            const int a = lane + 32 * i;
#pragma unroll
            for (int n = 0; n < N_PER_CTA; n++)
                s[n] += wv * tanh_fast(pv + pnS[n][a]);
        }
#pragma unroll
        for (int n = 0; n < N_PER_CTA; n++) {
            float v = s[n];
#pragma unroll
            for (int o = 16; o > 0; o >>= 1) v += __shfl_xor_sync(0xffffffffu, v, o);
            if (lane == 0) attnS[n][h] = v + b2v;
        }
    }
    __syncthreads();

    if (w < N_PER_CTA) {
        float v0 = attnS[w][lane];
        bool has1 = (lane + 32) < HLv;
        float v1 = has1 ? attnS[w][lane + 32] : -1e30f;
        float mx = fmaxf(v0, v1);
#pragma unroll
        for (int o = 16; o > 0; o >>= 1) mx = fmaxf(mx, __shfl_xor_sync(0xffffffffu, mx, o));
        float e0 = __expf(v0 - mx);
        float e1 = has1 ? __expf(v1 - mx) : 0.f;
        float ssum = e0 + e1;
#pragma unroll
        for (int o = 16; o > 0; o >>= 1) ssum += __shfl_xor_sync(0xffffffffu, ssum, o);
        float inv = 1.f / ssum;
        attnS[w][lane] = e0 * inv;
        if (has1) attnS[w][lane + 32] = e1 * inv;
    }
    __syncthreads();

    float* obase = out + (size_t)(b * NNv + nbase) * NEWSv;
    for (int d = tid; d < NEWSv; d += 256) {
        float acc[N_PER_CTA];
#pragma unroll
        for (int j = 0; j < N_PER_CTA; j++) acc[j] = 0.f;

        const float* srcp;
        int stride;
        if (d < INv) { srcp = logv + (size_t)b * HLv * INv + d; stride = INv; }
        else         { srcp = pos_emb + POSv + (d - INv);       stride = POSv; }

#pragma unroll 5
        for (int h = 0; h < HLv; h++) {
            float lv = srcp[h * stride];
#pragma unroll
            for (int j = 0; j < N_PER_CTA; j++) acc[j] += attnS[j][h] * lv;
        }
#pragma unroll
        for (int j = 0; j < N_PER_CTA; j++)
            obase[(size_t)j * NEWSv + d] = acc[j];
    }
}

// ---------------- launch ----------------
extern "C" void kernel_launch(void* const* d_in, const int* in_sizes, int n_in,
                              void* d_out, int out_size) {
    const float* logv = (const float*)d_in[0];   // [64,50,384]
    const int*   mask = (const int*)  d_in[1];   // [64,50]
    const float* news = (const float*)d_in[2];   // [64,64,384]
    const float* pos  = (const float*)d_in[3];   // [100,64]
    const float* W1   = (const float*)d_in[4];   // [256,896]
    const float* b1   = (const float*)d_in[5];   // [256]
    const float* W2   = (const float*)d_in[6];   // [1,256]
    const float* b2   = (const float*)d_in[7];   // [1]

    float* out_user = (float*)d_out;                       // [64,64,448]
    float* out_nf   = out_user + (size_t)BB * NNv * NEWSv; // [64,64,448]

    prep_kernel<<<51, 256>>>(pos, W1, b1);
    split_w1_kernel<<<ATTv, 224>>>(W1);
    asplit_kernel<<<(AROWS * INv / 4 + 255) / 256, 256>>>((const float4*)news,
                                                          (const float4*)logv);
    nf_kernel<<<BB * NNv, 128>>>((const float4*)news, (const float4*)pos,
                                 (float4*)out_nf);
    gemm_tc_kernel<<<dim3(4, 64, 2), 256>>>();
    attn_kernel<<<dim3(NNv / N_PER_CTA, BB), 256>>>(logv, mask, pos, W2, b2, out_user);
}